// round 10
// baseline (speedup 1.0000x reference)
#include <cuda_runtime.h>
#include <cuda_fp16.h>
#include <cstdint>

// LSTM fused cell, legacy tensor path (family-target ISA — no tcgen05 on compute_103).
// Prepass: fp32 -> fp16 RN, concat [x|h_prev] -> g_Ah, [Wx|Rh] -> g_Wh.
// Main: mma.sync.m16n8k16.f16 (fp32 accum), ldmatrix.x4, CTA 128M x 32N x 4 gates,
//       BK=64, 2-stage cp.async double buffer, one barrier per K-tile, 2 CTAs/SM.

#define B_DIM 16384
#define H_DIM 1024
#define K_DIM 2048
#define NKT 32          // 2048/64
#define BK 64
#define BM 128
#define BN 32           // per gate

#define PITCH 144       // bytes per smem row (128B data + 16B pad; 9 mod 8 = 1 -> conflict-free)
#define A_BYTES (BM * PITCH)            // 18432
#define B_BYTES (4 * BN * PITCH)        // 18432
#define STAGE (A_BYTES + B_BYTES)       // 36864
#define NSTAGE 2
#define SMEM_TOTAL (NSTAGE * STAGE)     // 73728 per CTA -> 2 CTAs/SM

__device__ __half g_Ah[(size_t)B_DIM * K_DIM];       // 67 MB
__device__ __half g_Wh[(size_t)4 * H_DIM * K_DIM];   // 17 MB

__device__ __forceinline__ uint32_t smem_u32(const void* p) {
    uint32_t a;
    asm("{ .reg .u64 t; cvta.to.shared.u64 t, %1; cvt.u32.u64 %0, t; }" : "=r"(a) : "l"(p));
    return a;
}
__device__ __forceinline__ void cp16(uint32_t saddr, const void* gaddr) {
    asm volatile("cp.async.cg.shared.global [%0], [%1], 16;" :: "r"(saddr), "l"(gaddr));
}
__device__ __forceinline__ void cp_commit() {
    asm volatile("cp.async.commit_group;");
}
template <int N>
__device__ __forceinline__ void cp_wait() {
    asm volatile("cp.async.wait_group %0;" :: "n"(N));
}
__device__ __forceinline__ void ldsm_x4(uint32_t r[4], uint32_t addr) {
    asm volatile("ldmatrix.sync.aligned.m8n8.x4.shared.b16 {%0,%1,%2,%3}, [%4];"
                 : "=r"(r[0]), "=r"(r[1]), "=r"(r[2]), "=r"(r[3]) : "r"(addr));
}
__device__ __forceinline__ void mma_f16(float c[4], const uint32_t a[4], const uint32_t b[2]) {
    asm volatile(
        "mma.sync.aligned.m16n8k16.row.col.f32.f16.f16.f32 "
        "{%0,%1,%2,%3}, {%4,%5,%6,%7}, {%8,%9}, {%0,%1,%2,%3};"
        : "+f"(c[0]), "+f"(c[1]), "+f"(c[2]), "+f"(c[3])
        : "r"(a[0]), "r"(a[1]), "r"(a[2]), "r"(a[3]), "r"(b[0]), "r"(b[1]));
}
__device__ __forceinline__ float sigmoidf_fast(float x) {
    return 1.0f / (1.0f + __expf(-x));
}

// ================= prepass =================
#define NA8 (B_DIM * 256u)
#define NW8 (4u * H_DIM * 256u)

__global__ void __launch_bounds__(256)
prep_kernel(const float* __restrict__ x, const float* __restrict__ h_prev,
            const float* __restrict__ Wx, const float* __restrict__ Rh) {
    unsigned i = blockIdx.x * 256u + threadIdx.x;
    const float* src;
    __half* dst;
    if (i < NA8) {
        unsigned b = i >> 8, kc = i & 255;
        unsigned k0 = kc * 8;
        src = (k0 < 1024) ? x + (size_t)b * 1024 + k0
                          : h_prev + (size_t)b * 1024 + (k0 - 1024);
        dst = &g_Ah[(size_t)i * 8];
    } else {
        unsigned j = i - NA8;
        unsigned row = j >> 8, kc = j & 255;
        unsigned k0 = kc * 8;
        src = (k0 < 1024) ? Wx + (size_t)row * 1024 + k0
                          : Rh + (size_t)row * 1024 + (k0 - 1024);
        dst = &g_Wh[(size_t)j * 8];
    }
    float4 v0 = *reinterpret_cast<const float4*>(src);
    float4 v1 = *reinterpret_cast<const float4*>(src + 4);
    __half2 h0 = __floats2half2_rn(v0.x, v0.y);
    __half2 h1 = __floats2half2_rn(v0.z, v0.w);
    __half2 h2 = __floats2half2_rn(v1.x, v1.y);
    __half2 h3 = __floats2half2_rn(v1.z, v1.w);
    uint4 o = make_uint4(*(uint32_t*)&h0, *(uint32_t*)&h1, *(uint32_t*)&h2, *(uint32_t*)&h3);
    *reinterpret_cast<uint4*>(dst) = o;
}

// ================= main GEMM + fused epilogue =================
__global__ void __launch_bounds__(256, 2)
lstm_fp16_kernel(const float* __restrict__ c_prev,
                 const float* __restrict__ bx,
                 const float* __restrict__ bh,
                 float* __restrict__ out) {
    extern __shared__ __align__(16) uint8_t smem[];

    const int t = threadIdx.x;
    const int lid = t & 31;
    const int wp = t >> 5;
    const int gid = lid >> 2;     // 0..7
    const int tig = lid & 3;      // 0..3
    const int wm = wp >> 1;       // 0..3 -> 32-row slab
    const int wn = wp & 1;        // 0..1 -> 16-col slab (per gate)

    const int mBase = blockIdx.y * BM;
    const int hBase = blockIdx.x * BN;

    const uint32_t sb = smem_u32(smem);

    // ldmatrix base byte-offsets within a stage
    uint32_t aOff[2];
#pragma unroll
    for (int mi = 0; mi < 2; ++mi)
        aOff[mi] = (uint32_t)((wm * 32 + mi * 16 + (lid & 15)) * PITCH + (lid >> 4) * 16);
    const uint32_t bOff = (uint32_t)(A_BYTES +
        (wn * 16 + ((lid >> 4) << 3) + (lid & 7)) * PITCH + ((lid >> 3) & 1) * 16);

    // cp.async mapping: each thread copies 64B (4 x 16B) of A and of B per tile.
    const int cRow = t >> 1;          // 0..127
    const int cHalf = t & 1;          // 64B half of the 128B row
    const size_t gA = (size_t)(mBase + cRow) * K_DIM + cHalf * 32;
    const int bG = cRow >> 5, bN = cRow & 31;
    const size_t gB = ((size_t)bG * H_DIM + hBase + bN) * K_DIM + cHalf * 32;
    const uint32_t sA = (uint32_t)(cRow * PITCH + cHalf * 64);
    const uint32_t sB = (uint32_t)(A_BYTES + cRow * PITCH + cHalf * 64);

    // ---- prologue: issue K-tile 0 into stage 0 ----
    {
        const uint32_t st = sb;
#pragma unroll
        for (int j = 0; j < 4; ++j) {
            cp16(st + sA + j * 16, &g_Ah[gA + j * 8]);
            cp16(st + sB + j * 16, &g_Wh[gB + j * 8]);
        }
        cp_commit();
    }

    float acc[4][2][2][4];
#pragma unroll
    for (int g = 0; g < 4; ++g)
#pragma unroll
        for (int mi = 0; mi < 2; ++mi)
#pragma unroll
            for (int ni = 0; ni < 2; ++ni)
#pragma unroll
                for (int k = 0; k < 4; ++k) acc[g][mi][ni][k] = 0.0f;

    for (int kt = 0; kt < NKT; ++kt) {
        // tile kt's copies arrived; barrier also guarantees all warps are done
        // reading the stage we are about to overwrite.
        cp_wait<0>();
        __syncthreads();

        // issue copies for tile kt+1 into the other stage
        if (kt + 1 < NKT) {
            const uint32_t st = sb + (uint32_t)((kt + 1) & 1) * STAGE;
            const int kOff = (kt + 1) * BK;
#pragma unroll
            for (int j = 0; j < 4; ++j) {
                cp16(st + sA + j * 16, &g_Ah[gA + kOff + j * 8]);
                cp16(st + sB + j * 16, &g_Wh[gB + kOff + j * 8]);
            }
            cp_commit();
        }

        // ---- compute on tile kt: 4 k16-steps ----
        const uint32_t sst = sb + (uint32_t)(kt & 1) * STAGE;
#pragma unroll
        for (int kk = 0; kk < 4; ++kk) {
            uint32_t a[2][4];
#pragma unroll
            for (int mi = 0; mi < 2; ++mi)
                ldsm_x4(a[mi], sst + aOff[mi] + kk * 32);
#pragma unroll
            for (int g = 0; g < 4; ++g) {
                uint32_t b[4];
                ldsm_x4(b, sst + bOff + g * (BN * PITCH) + kk * 32);
                mma_f16(acc[g][0][0], a[0], b + 0);
                mma_f16(acc[g][0][1], a[0], b + 2);
                mma_f16(acc[g][1][0], a[1], b + 0);
                mma_f16(acc[g][1][1], a[1], b + 2);
            }
        }
    }

    // ---- fused LSTM epilogue ----
#pragma unroll
    for (int mi = 0; mi < 2; ++mi) {
#pragma unroll
        for (int ni = 0; ni < 2; ++ni) {
#pragma unroll
            for (int rr = 0; rr < 2; ++rr) {
#pragma unroll
                for (int cc = 0; cc < 2; ++cc) {
                    const int r = mBase + wm * 32 + mi * 16 + gid + rr * 8;
                    const int col = hBase + wn * 16 + ni * 8 + tig * 2 + cc;
                    float pre[4];
#pragma unroll
                    for (int g = 0; g < 4; ++g) {
                        pre[g] = acc[g][mi][ni][rr * 2 + cc]
                               + __ldg(&bx[g * H_DIM + col])
                               + __ldg(&bh[g * H_DIM + col]);
                    }
                    const float z  = tanhf(pre[0]);
                    const float ig = sigmoidf_fast(pre[1]);
                    const float fg = sigmoidf_fast(pre[2]);
                    const float og = sigmoidf_fast(pre[3]);
                    const float cp = __ldg(&c_prev[(size_t)r * H_DIM + col]);
                    const float cn = fg * cp + ig * z;
                    const float hn = og * tanhf(cn);
                    out[(size_t)r * H_DIM + col] = hn;
                    out[(size_t)B_DIM * H_DIM + (size_t)r * H_DIM + col] = cn;
                }
            }
        }
    }
}

extern "C" void kernel_launch(void* const* d_in, const int* in_sizes, int n_in,
                              void* d_out, int out_size) {
    const float* x      = (const float*)d_in[0];
    const float* h_prev = (const float*)d_in[1];
    const float* c_prev = (const float*)d_in[2];
    const float* Wx     = (const float*)d_in[3];
    const float* bx     = (const float*)d_in[4];
    const float* Rh     = (const float*)d_in[5];
    const float* bh     = (const float*)d_in[6];
    float* out          = (float*)d_out;

    static int configured = 0;
    if (!configured) {
        cudaFuncSetAttribute(lstm_fp16_kernel,
                             cudaFuncAttributeMaxDynamicSharedMemorySize, SMEM_TOTAL);
        configured = 1;
    }

    prep_kernel<<<(NA8 + NW8) / 256, 256>>>(x, h_prev, Wx, Rh);

    dim3 grid(H_DIM / BN, B_DIM / BM, 1);   // (32, 128)
    lstm_fp16_kernel<<<grid, 256, SMEM_TOTAL>>>(c_prev, bx, bh, out);
}

// round 12
// speedup vs baseline: 1.2347x; 1.2347x over previous
#include <cuda_runtime.h>
#include <cuda_fp16.h>
#include <cstdint>

// LSTM fused cell, legacy tensor path (family-target ISA — no tcgen05 on compute_103).
// Prepass: fp32 -> fp16 RN, concat [x|h_prev] -> g_Ah, [Wx|Rh] -> g_Wh.
// Main: mma.sync.m16n8k16.f16 (fp32 accum), ldmatrix.x4, CTA 128M x 32N x 4 gates,
//       BK=32, 4-stage cp.async pipeline (3 tiles in flight), one barrier per K-tile,
//       2 CTAs/SM, fused LSTM epilogue.

#define B_DIM 16384
#define H_DIM 1024
#define K_DIM 2048
#define NKT 64
#define BK 32
#define BM 128
#define BN 32           // per gate

#define PITCH 80        // bytes per smem row (64B data + 16B pad)
#define A_BYTES (BM * PITCH)            // 10240
#define B_BYTES (4 * BN * PITCH)        // 10240
#define STAGE (A_BYTES + B_BYTES)       // 20480
#define NSTAGE 4
#define SMEM_TOTAL (NSTAGE * STAGE)     // 81920 per CTA -> 2 CTAs/SM (160KB < 228KB)

__device__ __half g_Ah[(size_t)B_DIM * K_DIM];       // 67 MB
__device__ __half g_Wh[(size_t)4 * H_DIM * K_DIM];   // 17 MB

__device__ __forceinline__ uint32_t smem_u32(const void* p) {
    uint32_t a;
    asm("{ .reg .u64 t; cvta.to.shared.u64 t, %1; cvt.u32.u64 %0, t; }" : "=r"(a) : "l"(p));
    return a;
}
__device__ __forceinline__ void cp16(uint32_t saddr, const void* gaddr) {
    asm volatile("cp.async.cg.shared.global [%0], [%1], 16;" :: "r"(saddr), "l"(gaddr));
}
__device__ __forceinline__ void cp_commit() {
    asm volatile("cp.async.commit_group;");
}
template <int N>
__device__ __forceinline__ void cp_wait() {
    asm volatile("cp.async.wait_group %0;" :: "n"(N));
}
__device__ __forceinline__ void ldsm_x4(uint32_t r[4], uint32_t addr) {
    asm volatile("ldmatrix.sync.aligned.m8n8.x4.shared.b16 {%0,%1,%2,%3}, [%4];"
                 : "=r"(r[0]), "=r"(r[1]), "=r"(r[2]), "=r"(r[3]) : "r"(addr));
}
__device__ __forceinline__ void mma_f16(float c[4], const uint32_t a[4], const uint32_t b[2]) {
    asm volatile(
        "mma.sync.aligned.m16n8k16.row.col.f32.f16.f16.f32 "
        "{%0,%1,%2,%3}, {%4,%5,%6,%7}, {%8,%9}, {%0,%1,%2,%3};"
        : "+f"(c[0]), "+f"(c[1]), "+f"(c[2]), "+f"(c[3])
        : "r"(a[0]), "r"(a[1]), "r"(a[2]), "r"(a[3]), "r"(b[0]), "r"(b[1]));
}
__device__ __forceinline__ float sigmoidf_fast(float x) {
    return 1.0f / (1.0f + __expf(-x));
}

// ================= prepass =================
#define NA8 (B_DIM * 256u)
#define NW8 (4u * H_DIM * 256u)

__global__ void __launch_bounds__(256)
prep_kernel(const float* __restrict__ x, const float* __restrict__ h_prev,
            const float* __restrict__ Wx, const float* __restrict__ Rh) {
    unsigned i = blockIdx.x * 256u + threadIdx.x;
    const float* src;
    __half* dst;
    if (i < NA8) {
        unsigned b = i >> 8, kc = i & 255;
        unsigned k0 = kc * 8;
        src = (k0 < 1024) ? x + (size_t)b * 1024 + k0
                          : h_prev + (size_t)b * 1024 + (k0 - 1024);
        dst = &g_Ah[(size_t)i * 8];
    } else {
        unsigned j = i - NA8;
        unsigned row = j >> 8, kc = j & 255;
        unsigned k0 = kc * 8;
        src = (k0 < 1024) ? Wx + (size_t)row * 1024 + k0
                          : Rh + (size_t)row * 1024 + (k0 - 1024);
        dst = &g_Wh[(size_t)j * 8];
    }
    float4 v0 = *reinterpret_cast<const float4*>(src);
    float4 v1 = *reinterpret_cast<const float4*>(src + 4);
    __half2 h0 = __floats2half2_rn(v0.x, v0.y);
    __half2 h1 = __floats2half2_rn(v0.z, v0.w);
    __half2 h2 = __floats2half2_rn(v1.x, v1.y);
    __half2 h3 = __floats2half2_rn(v1.z, v1.w);
    uint4 o = make_uint4(*(uint32_t*)&h0, *(uint32_t*)&h1, *(uint32_t*)&h2, *(uint32_t*)&h3);
    *reinterpret_cast<uint4*>(dst) = o;
}

// ================= main GEMM + fused epilogue =================
__global__ void __launch_bounds__(256, 2)
lstm_fp16_kernel(const float* __restrict__ c_prev,
                 const float* __restrict__ bx,
                 const float* __restrict__ bh,
                 float* __restrict__ out) {
    extern __shared__ __align__(16) uint8_t smem[];

    const int t = threadIdx.x;
    const int lid = t & 31;
    const int wp = t >> 5;
    const int gid = lid >> 2;     // 0..7
    const int tig = lid & 3;      // 0..3
    const int wm = wp >> 1;       // 0..3 -> 32-row slab
    const int wn = wp & 1;        // 0..1 -> 16-col slab (per gate)

    const int mBase = blockIdx.y * BM;
    const int hBase = blockIdx.x * BN;

    const uint32_t sb = smem_u32(smem);

    // ldmatrix base byte-offsets within a stage
    uint32_t aOff[2];
#pragma unroll
    for (int mi = 0; mi < 2; ++mi)
        aOff[mi] = (uint32_t)((wm * 32 + mi * 16 + (lid & 15)) * PITCH + (lid >> 4) * 16);
    const uint32_t bOff = (uint32_t)(A_BYTES +
        (wn * 16 + ((lid >> 4) << 3) + (lid & 7)) * PITCH + ((lid >> 3) & 1) * 16);

    // cp.async mapping: 512 16B-chunks for A (128 rows x 4) and for B.
    const int cRow = t >> 2;          // 0..63  (+64 for second pass)
    const int cC = t & 3;             // 16B chunk in row

    const size_t gA0 = (size_t)(mBase + cRow) * K_DIM + cC * 8;
    const size_t gA1 = (size_t)(mBase + cRow + 64) * K_DIM + cC * 8;
    const int bRowA = cRow;           // gate = row>>5, n = row&31
    const int bRowB = cRow + 64;
    const size_t gB0 = ((size_t)(bRowA >> 5) * H_DIM + hBase + (bRowA & 31)) * K_DIM + cC * 8;
    const size_t gB1 = ((size_t)(bRowB >> 5) * H_DIM + hBase + (bRowB & 31)) * K_DIM + cC * 8;
    const uint32_t sA0 = (uint32_t)(cRow * PITCH + cC * 16);
    const uint32_t sA1 = (uint32_t)((cRow + 64) * PITCH + cC * 16);
    const uint32_t sB0 = (uint32_t)(A_BYTES + bRowA * PITCH + cC * 16);
    const uint32_t sB1 = (uint32_t)(A_BYTES + bRowB * PITCH + cC * 16);

    // ---- prologue: issue K-tiles 0..2 ----
#pragma unroll
    for (int kt = 0; kt < NSTAGE - 1; ++kt) {
        const uint32_t st = sb + (uint32_t)kt * STAGE;
        const int kOff = kt * BK;
        cp16(st + sA0, &g_Ah[gA0 + kOff]);
        cp16(st + sA1, &g_Ah[gA1 + kOff]);
        cp16(st + sB0, &g_Wh[gB0 + kOff]);
        cp16(st + sB1, &g_Wh[gB1 + kOff]);
        cp_commit();
    }

    float acc[4][2][2][4];
#pragma unroll
    for (int g = 0; g < 4; ++g)
#pragma unroll
        for (int mi = 0; mi < 2; ++mi)
#pragma unroll
            for (int ni = 0; ni < 2; ++ni)
#pragma unroll
                for (int k = 0; k < 4; ++k) acc[g][mi][ni][k] = 0.0f;

    int stage = 0;
    for (int kt = 0; kt < NKT; ++kt) {
        // Tile kt is resident when <= (#groups issued after kt) remain pending.
        if (kt < NKT - 2)       cp_wait<2>();
        else if (kt == NKT - 2) cp_wait<1>();
        else                    cp_wait<0>();
        __syncthreads();

        // issue copies for tile kt+3 into the stage being freed (4 tiles old)
        if (kt + NSTAGE - 1 < NKT) {
            int s3 = stage + NSTAGE - 1;
            if (s3 >= NSTAGE) s3 -= NSTAGE;
            const uint32_t st = sb + (uint32_t)s3 * STAGE;
            const int kOff = (kt + NSTAGE - 1) * BK;
            cp16(st + sA0, &g_Ah[gA0 + kOff]);
            cp16(st + sA1, &g_Ah[gA1 + kOff]);
            cp16(st + sB0, &g_Wh[gB0 + kOff]);
            cp16(st + sB1, &g_Wh[gB1 + kOff]);
            cp_commit();
        }

        // ---- compute on tile kt ----
        const uint32_t sst = sb + (uint32_t)stage * STAGE;
#pragma unroll
        for (int kk = 0; kk < 2; ++kk) {
            uint32_t a[2][4];
#pragma unroll
            for (int mi = 0; mi < 2; ++mi)
                ldsm_x4(a[mi], sst + aOff[mi] + kk * 32);
#pragma unroll
            for (int g = 0; g < 4; ++g) {
                uint32_t b[4];
                ldsm_x4(b, sst + bOff + g * (BN * PITCH) + kk * 32);
                mma_f16(acc[g][0][0], a[0], b + 0);
                mma_f16(acc[g][0][1], a[0], b + 2);
                mma_f16(acc[g][1][0], a[1], b + 0);
                mma_f16(acc[g][1][1], a[1], b + 2);
            }
        }

        stage = (stage + 1 == NSTAGE) ? 0 : stage + 1;
    }

    // ---- fused LSTM epilogue ----
#pragma unroll
    for (int mi = 0; mi < 2; ++mi) {
#pragma unroll
        for (int ni = 0; ni < 2; ++ni) {
#pragma unroll
            for (int rr = 0; rr < 2; ++rr) {
#pragma unroll
                for (int cc = 0; cc < 2; ++cc) {
                    const int r = mBase + wm * 32 + mi * 16 + gid + rr * 8;
                    const int col = hBase + wn * 16 + ni * 8 + tig * 2 + cc;
                    float pre[4];
#pragma unroll
                    for (int g = 0; g < 4; ++g) {
                        pre[g] = acc[g][mi][ni][rr * 2 + cc]
                               + __ldg(&bx[g * H_DIM + col])
                               + __ldg(&bh[g * H_DIM + col]);
                    }
                    const float z  = tanhf(pre[0]);
                    const float ig = sigmoidf_fast(pre[1]);
                    const float fg = sigmoidf_fast(pre[2]);
                    const float og = sigmoidf_fast(pre[3]);
                    const float cp = __ldg(&c_prev[(size_t)r * H_DIM + col]);
                    const float cn = fg * cp + ig * z;
                    const float hn = og * tanhf(cn);
                    out[(size_t)r * H_DIM + col] = hn;
                    out[(size_t)B_DIM * H_DIM + (size_t)r * H_DIM + col] = cn;
                }
            }
        }
    }
}

extern "C" void kernel_launch(void* const* d_in, const int* in_sizes, int n_in,
                              void* d_out, int out_size) {
    const float* x      = (const float*)d_in[0];
    const float* h_prev = (const float*)d_in[1];
    const float* c_prev = (const float*)d_in[2];
    const float* Wx     = (const float*)d_in[3];
    const float* bx     = (const float*)d_in[4];
    const float* Rh     = (const float*)d_in[5];
    const float* bh     = (const float*)d_in[6];
    float* out          = (float*)d_out;

    static int configured = 0;
    if (!configured) {
        cudaFuncSetAttribute(lstm_fp16_kernel,
                             cudaFuncAttributeMaxDynamicSharedMemorySize, SMEM_TOTAL);
        configured = 1;
    }

    prep_kernel<<<(NA8 + NW8) / 256, 256>>>(x, h_prev, Wx, Rh);

    dim3 grid(H_DIM / BN, B_DIM / BM, 1);   // (32, 128)
    lstm_fp16_kernel<<<grid, 256, SMEM_TOTAL>>>(c_prev, bx, bh, out);
}